// round 7
// baseline (speedup 1.0000x reference)
#include <cuda_runtime.h>
#include <math.h>

#define B_IMGS   64
#define NBLK     4096
#define NLIN     16384
#define NCHR     16384
#define TOPK     100
#define KSEL     128      // exact top-K superset size by logit
#define MTGT     160      // stop bisection once survivor count <= this
#define NT       512
#define FASTCAP  512
#define NSEG     (B_IMGS * 3)

// threshold guess keys (monotone float->uint), per level
#define GK0 0xBFC00000u   // logit 1.5  (N=4096)
#define GH0 0xC0800000u   // logit 4.0
#define GK1 0xC0100000u   // logit 2.25 (N=16384)
#define GH1 0xC0980000u   // logit 4.75

// Output layout (float32), reference return order (*blk, *lin, *chr):
//  blk_data [64,100,4]  @ 0       blk_scores @ 25600   blk_keep @ 32000
//  lin_data [64,100,4]  @ 38400   lin_scores @ 64000   lin_keep @ 70400
//  chr_data [64,100,16] @ 76800   chr_scores @ 179200  chr_keep @ 185600

__device__ int   g_cnt[NSEG];                 // zero-init at load; finish kernel re-zeroes
__device__ uint2 g_cand[NSEG * FASTCAP];      // (key, idx) survivors per segment

__device__ __forceinline__ unsigned int fkey(float f) {
    unsigned int u = __float_as_uint(f);
    return u ^ (((unsigned int)((int)u >> 31)) | 0x80000000u);
}

// ============================ kernel 1: filter ============================
__global__ void __launch_bounds__(NT)
filter_kernel(const float* __restrict__ blk_logit,
              const float* __restrict__ lin_logit,
              const float* __restrict__ chr_logit)
{
    const int slice = blockIdx.x;     // 0..7
    const int b     = blockIdx.y;
    const int lvl   = blockIdx.z;
    const int tid   = threadIdx.x;
    const int seg   = lvl * B_IMGS + b;

    if (lvl == 0) {
        const float* lb = blk_logit + (size_t)b * NBLK;
        int e = slice * NT + tid;                       // 0..4095
        unsigned int k = fkey(lb[e]);
        if (k >= GK0) {
            int p = atomicAdd(&g_cnt[seg], 1);
            if (p < FASTCAP) g_cand[seg * FASTCAP + p] = make_uint2(k, (unsigned int)e);
        }
    } else {
        const float* lb = ((lvl == 1) ? lin_logit : chr_logit) + (size_t)b * NLIN;
        int q = slice * NT + tid;                       // 0..4095 float4s
        float4 v = ((const float4*)lb)[q];
        unsigned int k0 = fkey(v.x), k1 = fkey(v.y), k2 = fkey(v.z), k3 = fkey(v.w);
        int n = (k0 >= GK1) + (k1 >= GK1) + (k2 >= GK1) + (k3 >= GK1);
        if (n) {
            int p = atomicAdd(&g_cnt[seg], n);
            uint2* dst = g_cand + seg * FASTCAP;
            if (k0 >= GK1) { if (p < FASTCAP) dst[p] = make_uint2(k0, 4u * q + 0u); ++p; }
            if (k1 >= GK1) { if (p < FASTCAP) dst[p] = make_uint2(k1, 4u * q + 1u); ++p; }
            if (k2 >= GK1) { if (p < FASTCAP) dst[p] = make_uint2(k2, 4u * q + 2u); ++p; }
            if (k3 >= GK1) { if (p < FASTCAP) dst[p] = make_uint2(k3, 4u * q + 3u); ++p; }
        }
    }
}

// ============================ kernel 2: finish ============================
struct __align__(16) SharedState {
    unsigned int adj[TOPK][4];
    float4 sdat4[TOPK][4];
    float4 sbox4[TOPK];
    unsigned long long fckey[FASTCAP];
    unsigned long long wkeys[16];
    unsigned int ckey[FASTCAP];
    int          cidx[FASTCAP];
    float sval[TOPK];
    int   sidx[TOPK];
    float sarea[TOPK];
    float sbelong[TOPK];
    int   skeep[TOPK];
    int   klist[TOPK];
    unsigned int keepw[4];
    int totals[32];
    int cnt;
    int cnt2;
    int gcnt;
    int kcnt;
    int argmax_idx;
};

template<int LOC, int LEVEL>
__device__ __forceinline__ void pp_body(
    SharedState& sm, int b, int tid,
    const float* __restrict__ lb,
    const float* __restrict__ blk_raw,
    const float* __restrict__ lin_raw,
    const float* __restrict__ chr_raw,
    const float* __restrict__ tsz,
    float* __restrict__ out)
{
    const int N = LOC * NT;
    const int seg = LEVEL * B_IMGS + b;
    constexpr unsigned int GK = (LEVEL == 0) ? GK0 : GK1;
    constexpr unsigned int GH = (LEVEL == 0) ? GH0 : GH1;

    sm.fckey[tid] = 0ull;
    if (tid < 32) sm.totals[tid] = 0;
    if (tid == 0) {
        sm.cnt = 0; sm.cnt2 = 0; sm.kcnt = 0; sm.argmax_idx = 0;
        sm.gcnt = g_cnt[seg];
        g_cnt[seg] = 0;                  // reset for next invocation
    }
    __syncthreads();
    const int cG = sm.gcnt;

    unsigned int mykey = 0u;
    int myidx = 0;
    unsigned int lo, hi;
    int cg, cnt_cur;

    if (cG >= KSEL && cG <= FASTCAP) {
        // ---- fast path: candidates already filtered by kernel 1 ----
        if (tid < cG) {
            uint2 c = g_cand[seg * FASTCAP + tid];
            mykey = c.x; myidx = (int)c.y;
        }
        cg = cG; lo = GK; hi = GH; cnt_cur = cG;
    } else {
        // ---- slow path: exact in-CTA search (correctness net; rare) ----
        unsigned int lk[LOC];
        const float4* lb4 = (const float4*)lb;
#pragma unroll
        for (int r4 = 0; r4 < LOC / 4; ++r4) {
            float4 v = lb4[tid + r4 * NT];
            lk[4 * r4 + 0] = fkey(v.x);
            lk[4 * r4 + 1] = fkey(v.y);
            lk[4 * r4 + 2] = fkey(v.z);
            lk[4 * r4 + 3] = fkey(v.w);
        }
        unsigned int prefix = 0u;
        cnt_cur = N;
        for (int bit = 31; bit >= 0; --bit) {
            if (cnt_cur <= FASTCAP) break;
            unsigned int cand = prefix | (1u << bit);
            unsigned int c = 0;
#pragma unroll
            for (int r = 0; r < LOC; ++r) c += (lk[r] >= cand) ? 1u : 0u;
            c = __reduce_add_sync(0xFFFFFFFFu, c);
            if ((tid & 31) == 0 && c) atomicAdd(&sm.totals[bit], (int)c);
            __syncthreads();
            int tot = sm.totals[bit];
            if (tot >= KSEL) { prefix = cand; cnt_cur = tot; }
        }
#pragma unroll
        for (int r4 = 0; r4 < LOC / 4; ++r4) {
#pragma unroll
            for (int c = 0; c < 4; ++c) {
                unsigned int k = lk[4 * r4 + c];
                if (k >= prefix) {
                    int p = atomicAdd(&sm.cnt, 1);
                    if (p < FASTCAP) { sm.ckey[p] = k; sm.cidx[p] = 4 * (tid + r4 * NT) + c; }
                }
            }
        }
        __syncthreads();
        cg = min(sm.cnt, FASTCAP);
        if (tid < cg) { mykey = sm.ckey[tid]; myidx = sm.cidx[tid]; }
        lo = prefix; hi = 0xFFFFFFFFu;
    }

    // ---- value bisection: shrink survivor count toward [KSEL, MTGT] ----
    int cnt_m = cnt_cur;
    for (int it = 0; it < 6 && cnt_m > MTGT; ++it) {
        unsigned int mid = lo + ((hi - lo) >> 1);
        int c = __syncthreads_count((tid < cg) && (mykey >= mid));
        if (c >= KSEL) { lo = mid; cnt_m = c; } else hi = mid;
    }

    // ---- compact final survivors, fast f32 sigmoid, composite key ----
    if (tid < cg && mykey >= lo) {
        int p = atomicAdd(&sm.cnt2, 1);
        unsigned int u = mykey ^ ((mykey & 0x80000000u) ? 0x80000000u : 0xFFFFFFFFu);
        float x = __uint_as_float(u);
        float prob = 1.0f / (1.0f + __expf(-x));
        sm.fckey[p] = ((unsigned long long)__float_as_uint(prob) << 32)
                      | (unsigned int)(~(unsigned int)myidx);
    }
    __syncthreads();
    const int M = min(sm.cnt2, FASTCAP);   // >= KSEL

    // ---- rank by composite key desc == (prob desc, index asc); x4 unrolled ----
    if (tid < M) {
        const unsigned long long mk = sm.fckey[tid];
        int rank = 0;
        const int Mp = (M + 3) & ~3;
        for (int j = 0; j < Mp; j += 4) {
            rank += (sm.fckey[j]     > mk) ? 1 : 0;
            rank += (sm.fckey[j + 1] > mk) ? 1 : 0;
            rank += (sm.fckey[j + 2] > mk) ? 1 : 0;
            rank += (sm.fckey[j + 3] > mk) ? 1 : 0;
        }
        if (rank < TOPK) {
            sm.sval[rank] = __uint_as_float((unsigned int)(mk >> 32));
            sm.sidx[rank] = (int)(~(unsigned int)(mk & 0xFFFFFFFFu));
        }
    }
    __syncthreads();

    const float hh = tsz[2 * b + 0];   // img_h
    const float ww = tsz[2 * b + 1];   // img_w

    // ---- char level: spread scattered ctrl-point gather over 400 threads ----
    if (LEVEL == 2) {
        if (tid < TOPK * 4) {
            const int k = tid >> 2, q = tid & 3;
            const int si = sm.sidx[k];
            float4 v = ((const float4*)(chr_raw + ((size_t)b * NCHR + (size_t)si) * 16))[q];
            v.x *= hh; v.y *= ww; v.z *= hh; v.w *= ww;
            sm.sdat4[k][q] = v;
        }
        __syncthreads();
    }

    // ---- per-detection geometry ----
    if (tid < TOPK) {
        const int k  = tid;
        const int si = sm.sidx[k];
        float x1, y1, x2, y2;
        float4 p;

        if (LEVEL == 1) {
            p = ((const float4*)(blk_raw + ((size_t)b * NBLK + (size_t)(si >> 2)) * 4))[0];
        } else if (LEVEL == 2) {
            p = ((const float4*)(lin_raw + ((size_t)b * NLIN + (size_t)si) * 4))[0];
        }

        if (LEVEL == 2) {
            float ctrl[16];
#pragma unroll
            for (int q = 0; q < 4; ++q) {
                float4 v = sm.sdat4[k][q];
                ctrl[4 * q + 0] = v.x; ctrl[4 * q + 1] = v.y;
                ctrl[4 * q + 2] = v.z; ctrl[4 * q + 3] = v.w;
            }
            float mnx = 1e30f, mny = 1e30f, mxx = -1e30f, mxy = -1e30f;
#pragma unroll
            for (int s = 0; s < 10; ++s) {
                float t  = (float)s * (1.0f / 9.0f);
                float ti = 1.0f - t;
                float b0 = ti * ti * ti;
                float b1 = 3.0f * t * ti * ti;
                float b2 = 3.0f * t * t * ti;
                float b3 = t * t * t;
                float xt = b0 * ctrl[0] + b1 * ctrl[2]  + b2 * ctrl[4]  + b3 * ctrl[6];
                float yt = b0 * ctrl[1] + b1 * ctrl[3]  + b2 * ctrl[5]  + b3 * ctrl[7];
                float xb = b0 * ctrl[8] + b1 * ctrl[10] + b2 * ctrl[12] + b3 * ctrl[14];
                float yb = b0 * ctrl[9] + b1 * ctrl[11] + b2 * ctrl[13] + b3 * ctrl[15];
                mnx = fminf(mnx, fminf(xt, xb));
                mny = fminf(mny, fminf(yt, yb));
                mxx = fmaxf(mxx, fmaxf(xt, xb));
                mxy = fmaxf(mxy, fmaxf(yt, yb));
            }
            x1 = mnx; y1 = mny; x2 = mxx; y2 = mxy;
        } else {
            float4 v = (LEVEL == 0)
                ? ((const float4*)(blk_raw + ((size_t)b * NBLK + (size_t)si) * 4))[0]
                : ((const float4*)(lin_raw + ((size_t)b * NLIN + (size_t)si) * 4))[0];
            x1 = (v.x - 0.5f * v.z) * ww;
            y1 = (v.y - 0.5f * v.w) * hh;
            x2 = (v.x + 0.5f * v.z) * ww;
            y2 = (v.y + 0.5f * v.w) * hh;
            if (LEVEL == 0) {
                x1 = fminf(fmaxf(x1, 0.0f), ww);
                y1 = fminf(fmaxf(y1, 0.0f), hh);
                x2 = fminf(fmaxf(x2, 0.0f), ww);
                y2 = fminf(fmaxf(y2, 0.0f), hh);
            }
            float4 d; d.x = x1; d.y = y1; d.z = x2; d.w = y2;
            sm.sdat4[k][0] = d;
        }

        float4 bx; bx.x = x1; bx.y = y1; bx.z = x2; bx.w = y2;
        sm.sbox4[k] = bx;
        sm.sarea[k] = (x2 - x1) * (y2 - y1);

        bool kp   = sm.sval[k] > 0.1f;
        bool anyk = sm.sval[0] > 0.1f;
        if (!anyk) kp = (k == 0);
        sm.skeep[k] = kp ? 1 : 0;

        if (LEVEL > 0) {
            float px1 = (p.x - 0.5f * p.z) * ww;
            float py1 = (p.y - 0.5f * p.w) * hh;
            float px2 = (p.x + 0.5f * p.z) * ww;
            float py2 = (p.y + 0.5f * p.w) * hh;
            float ix1 = fmaxf(x1, px1);
            float iy1 = fmaxf(y1, py1);
            float ix2 = fminf(x2, px2);
            float iy2 = fminf(y2, py2);
            float inter = fmaxf(ix2 - ix1, 0.0f) * fmaxf(iy2 - iy1, 0.0f);
            float carea = (x2 - x1) * (y2 - y1);
            sm.sbelong[k] = inter / (carea + 1e-6f);
        }
    }
    __syncthreads();

    // ---- belong validity + fallback (lines / chars), parallel argmax ----
    if (LEVEL > 0) {
        const bool in = (tid < TOPK) && (sm.skeep[tid] != 0);
        const float bl = in ? sm.sbelong[tid] : 0.0f;
        int any_vk = __syncthreads_count(in && (bl > 0.6f));
        unsigned long long key = in
            ? (((unsigned long long)__float_as_uint(bl) << 32) | (unsigned int)(~(unsigned int)tid))
            : 0ull;
#pragma unroll
        for (int off = 16; off > 0; off >>= 1) {
            unsigned long long o = __shfl_down_sync(0xFFFFFFFFu, key, off);
            key = (o > key) ? o : key;
        }
        if ((tid & 31) == 0) sm.wkeys[tid >> 5] = key;
        __syncthreads();
        if (tid == 0) {
            unsigned long long best = 0ull;
#pragma unroll
            for (int w = 0; w < 16; ++w) best = (sm.wkeys[w] > best) ? sm.wkeys[w] : best;
            sm.argmax_idx = (best == 0ull) ? 0 : (int)(~(unsigned int)(best & 0xFFFFFFFFu));
        }
        __syncthreads();
        if (tid < TOPK) {
            bool valid = sm.sbelong[tid] > 0.6f;
            if (any_vk == 0) valid = (tid == sm.argmax_idx);
            if (!valid) sm.skeep[tid] = 0;
        }
        __syncthreads();
    }

    // ---- keep ballot + compact kept-index list ----
    if (tid < 128) {
        bool kp = (tid < TOPK) && (sm.skeep[tid] != 0);
        unsigned int m = __ballot_sync(0xFFFFFFFFu, kp);
        if ((tid & 31) == 0) sm.keepw[tid >> 5] = m;
    }
    if (tid < TOPK && sm.skeep[tid]) {
        int p = atomicAdd(&sm.kcnt, 1);
        sm.klist[p] = tid;
    }
    __syncthreads();

    // ---- NMS adjacency: only rows for initially-kept boxes ----
    {
        const int warp = tid >> 5, lane = tid & 31;
        const int ntask = sm.kcnt * 4;
        for (int task = warp; task < ntask; task += NT / 32) {
            const int i = sm.klist[task >> 2], w = task & 3;
            unsigned int m = 0u;
            if (i < 32 * (w + 1)) {
                const int j = w * 32 + lane;
                bool pred = false;
                if (j < TOPK && j > i) {
                    float4 bi_ = sm.sbox4[i];
                    float4 bj_ = sm.sbox4[j];
                    float ix1 = fmaxf(bi_.x, bj_.x);
                    float iy1 = fmaxf(bi_.y, bj_.y);
                    float ix2 = fminf(bi_.z, bj_.z);
                    float iy2 = fminf(bi_.w, bj_.w);
                    float inter = fmaxf(ix2 - ix1, 0.0f) * fmaxf(iy2 - iy1, 0.0f);
                    pred = inter > 0.1f * (sm.sarea[i] + sm.sarea[j] - inter);
                }
                m = __ballot_sync(0xFFFFFFFFu, pred);
            }
            if (lane == 0) sm.adj[i][w] = m;
        }
    }
    __syncthreads();

    // ---- suppression scan: ffs-jump over still-kept boxes only ----
    if (tid == 0) {
        unsigned int kk0 = sm.keepw[0], kk1 = sm.keepw[1], kk2 = sm.keepw[2], kk3 = sm.keepw[3];
        const uint4* adj4 = (const uint4*)sm.adj;
#pragma unroll
        for (int w = 0; w < 4; ++w) {
            unsigned int cur = (w == 0) ? kk0 : (w == 1) ? kk1 : (w == 2) ? kk2 : kk3;
            unsigned int m = cur;
            while (m) {
                int bitp = __ffs(m) - 1;
                int i = 32 * w + bitp;
                uint4 a = adj4[i];
                kk0 &= ~a.x; kk1 &= ~a.y; kk2 &= ~a.z; kk3 &= ~a.w;
                cur = (w == 0) ? kk0 : (w == 1) ? kk1 : (w == 2) ? kk2 : kk3;
                m = cur & ((0xFFFFFFFFu << bitp) << 1);
            }
        }
        sm.keepw[0] = kk0; sm.keepw[1] = kk1; sm.keepw[2] = kk2; sm.keepw[3] = kk3;
    }
    __syncthreads();

    // ---- write outputs ----
    constexpr size_t data_off  = (LEVEL == 0) ? 0      : (LEVEL == 1) ? 38400 : 76800;
    constexpr size_t score_off = (LEVEL == 0) ? 25600  : (LEVEL == 1) ? 64000 : 179200;
    constexpr size_t keep_off  = (LEVEL == 0) ? 32000  : (LEVEL == 1) ? 70400 : 185600;
    const float4 z4 = make_float4(0.f, 0.f, 0.f, 0.f);

    if (LEVEL == 2) {
        float4* dp4 = (float4*)(out + data_off + (size_t)b * TOPK * 16);
        if (tid < TOPK * 4) {
            const int k = tid >> 2, q = tid & 3;
            bool kp = (sm.keepw[k >> 5] >> (k & 31)) & 1u;
            dp4[tid] = kp ? sm.sdat4[k][q] : z4;
        }
    } else {
        float4* dp4 = (float4*)(out + data_off + (size_t)b * TOPK * 4);
        if (tid < TOPK) {
            bool kp = (sm.keepw[tid >> 5] >> (tid & 31)) & 1u;
            dp4[tid] = kp ? sm.sdat4[tid][0] : z4;
        }
    }
    if (tid < TOPK) {
        bool kp = (sm.keepw[tid >> 5] >> (tid & 31)) & 1u;
        out[score_off + (size_t)b * TOPK + tid] = kp ? sm.sval[tid] : 0.0f;
        out[keep_off  + (size_t)b * TOPK + tid] = kp ? 1.0f : 0.0f;
    }
}

__global__ void __launch_bounds__(NT)
finish_kernel(const float* __restrict__ blk_logit,
              const float* __restrict__ lin_logit,
              const float* __restrict__ chr_logit,
              const float* __restrict__ blk_raw,
              const float* __restrict__ lin_raw,
              const float* __restrict__ chr_raw,
              const float* __restrict__ tsz,
              float* __restrict__ out)
{
    __shared__ SharedState sm;
    const int b     = blockIdx.x;
    const int level = blockIdx.y;
    const int tid   = threadIdx.x;

    if (level == 0) {
        pp_body<8, 0>(sm, b, tid, blk_logit + (size_t)b * NBLK,
                      blk_raw, lin_raw, chr_raw, tsz, out);
    } else if (level == 1) {
        pp_body<32, 1>(sm, b, tid, lin_logit + (size_t)b * NLIN,
                       blk_raw, lin_raw, chr_raw, tsz, out);
    } else {
        pp_body<32, 2>(sm, b, tid, chr_logit + (size_t)b * NCHR,
                       blk_raw, lin_raw, chr_raw, tsz, out);
    }
}

extern "C" void kernel_launch(void* const* d_in, const int* in_sizes, int n_in,
                              void* d_out, int out_size) {
    (void)in_sizes; (void)n_in; (void)out_size;
    const float* blk_logit = (const float*)d_in[0];
    const float* lin_logit = (const float*)d_in[1];
    const float* chr_logit = (const float*)d_in[2];
    const float* blk_raw   = (const float*)d_in[3];
    const float* lin_raw   = (const float*)d_in[4];
    const float* chr_raw   = (const float*)d_in[5];
    const float* tsz       = (const float*)d_in[6];

    filter_kernel<<<dim3(8, B_IMGS, 3), NT>>>(blk_logit, lin_logit, chr_logit);
    finish_kernel<<<dim3(B_IMGS, 3), NT>>>(blk_logit, lin_logit, chr_logit,
                                           blk_raw, lin_raw, chr_raw, tsz,
                                           (float*)d_out);
}

// round 8
// speedup vs baseline: 2.0847x; 2.0847x over previous
#include <cuda_runtime.h>
#include <math.h>

#define B_IMGS   64
#define NBLK     4096
#define NLIN     16384
#define NCHR     16384
#define TOPK     100
#define KSEL     128      // exact top-K superset size by logit
#define MTGT     160      // stop bisection once survivor count <= this
#define NT       512
#define FASTCAP  512

// threshold guess keys (monotone float->uint), per level
#define GK0 0xBFC00000u   // logit 1.5  (N=4096)
#define GH0 0xC0800000u   // logit 4.0
#define GK1 0xC0100000u   // logit 2.25 (N=16384)
#define GH1 0xC0980000u   // logit 4.75

// Output layout (float32), reference return order (*blk, *lin, *chr):
//  blk_data [64,100,4]  @ 0       blk_scores @ 25600   blk_keep @ 32000
//  lin_data [64,100,4]  @ 38400   lin_scores @ 64000   lin_keep @ 70400
//  chr_data [64,100,16] @ 76800   chr_scores @ 179200  chr_keep @ 185600

struct __align__(16) SharedState {
    unsigned int adj[TOPK][4];
    float4 sdat4[TOPK][4];
    float4 sbox4[TOPK];
    unsigned long long fckey[FASTCAP];
    unsigned long long wkeys[16];
    unsigned int ckey[FASTCAP];
    int          cidx[FASTCAP];
    float sval[TOPK];
    int   sidx[TOPK];
    float sarea[TOPK];
    float sbelong[TOPK];
    int   skeep[TOPK];
    int   klist[TOPK];
    unsigned int keepw[4];
    int totals[32];
    int cnt;
    int cnt2;
    int kcnt;
    int argmax_idx;
};

__device__ __forceinline__ unsigned int fkey(float f) {
    unsigned int u = __float_as_uint(f);
    return u ^ (((unsigned int)((int)u >> 31)) | 0x80000000u);
}

template<int LOC, int LEVEL>
__device__ __forceinline__ void pp_body(
    SharedState& sm, int b, int tid,
    const float* __restrict__ lb,
    const float* __restrict__ blk_raw,
    const float* __restrict__ lin_raw,
    const float* __restrict__ chr_raw,
    const float* __restrict__ tsz,
    float* __restrict__ out)
{
    const int N = LOC * NT;
    constexpr unsigned int GK = (LEVEL == 0) ? GK0 : GK1;
    constexpr unsigned int GH = (LEVEL == 0) ? GH0 : GH1;

    // ---- load logits via float4 -> monotone uint keys (registers) ----
    unsigned int lk[LOC];
    {
        const float4* lb4 = (const float4*)lb;
#pragma unroll
        for (int r4 = 0; r4 < LOC / 4; ++r4) {
            float4 v = lb4[tid + r4 * NT];
            lk[4 * r4 + 0] = fkey(v.x);
            lk[4 * r4 + 1] = fkey(v.y);
            lk[4 * r4 + 2] = fkey(v.z);
            lk[4 * r4 + 3] = fkey(v.w);
        }
    }

    sm.fckey[tid] = 0ull;               // zero-pad for unrolled rank loop
    if (tid < 32) sm.totals[tid] = 0;
    if (tid == 0) { sm.cnt = 0; sm.cnt2 = 0; sm.kcnt = 0; sm.argmax_idx = 0; }
    __syncthreads();

    // ---- merged guess gather: append key >= GK directly to shared ----
#pragma unroll
    for (int r4 = 0; r4 < LOC / 4; ++r4) {
#pragma unroll
        for (int c = 0; c < 4; ++c) {
            unsigned int k = lk[4 * r4 + c];
            if (k >= GK) {
                int p = atomicAdd(&sm.cnt, 1);
                if (p < FASTCAP) { sm.ckey[p] = k; sm.cidx[p] = 4 * (tid + r4 * NT) + c; }
            }
        }
    }
    __syncthreads();
    const int cG = sm.cnt;

    unsigned int lo, hi;
    int cg, cnt_cur;
    if (cG >= KSEL && cG <= FASTCAP) {
        cg = cG; lo = GK; hi = GH; cnt_cur = cG;
    } else {
        // ---- fallback: exact bitwise search on registers (correctness net) ----
        __syncthreads();
        if (tid == 0) sm.cnt = 0;
        __syncthreads();
        unsigned int prefix = 0u;
        cnt_cur = N;
        for (int bit = 31; bit >= 0; --bit) {
            if (cnt_cur <= FASTCAP) break;
            unsigned int cand = prefix | (1u << bit);
            unsigned int c = 0;
#pragma unroll
            for (int r = 0; r < LOC; ++r) c += (lk[r] >= cand) ? 1u : 0u;
            c = __reduce_add_sync(0xFFFFFFFFu, c);
            if ((tid & 31) == 0 && c) atomicAdd(&sm.totals[bit], (int)c);
            __syncthreads();
            int tot = sm.totals[bit];
            if (tot >= KSEL) { prefix = cand; cnt_cur = tot; }
        }
#pragma unroll
        for (int r4 = 0; r4 < LOC / 4; ++r4) {
#pragma unroll
            for (int c = 0; c < 4; ++c) {
                unsigned int k = lk[4 * r4 + c];
                if (k >= prefix) {
                    int p = atomicAdd(&sm.cnt, 1);
                    if (p < FASTCAP) { sm.ckey[p] = k; sm.cidx[p] = 4 * (tid + r4 * NT) + c; }
                }
            }
        }
        __syncthreads();
        cg = min(sm.cnt, FASTCAP);
        lo = prefix; hi = 0xFFFFFFFFu;
    }

    const unsigned int mykey = (tid < cg) ? sm.ckey[tid] : 0u;
    const int myidx = (tid < cg) ? sm.cidx[tid] : 0;

    // ---- value bisection: shrink survivor count toward [KSEL, MTGT] ----
    int cnt_m = cnt_cur;
    for (int it = 0; it < 6 && cnt_m > MTGT; ++it) {
        unsigned int mid = lo + ((hi - lo) >> 1);
        int c = __syncthreads_count((tid < cg) && (mykey >= mid));
        if (c >= KSEL) { lo = mid; cnt_m = c; } else hi = mid;
    }

    // ---- compact final survivors, fast f32 sigmoid, composite key ----
    if (tid < cg && mykey >= lo) {
        int p = atomicAdd(&sm.cnt2, 1);
        unsigned int u = mykey ^ ((mykey & 0x80000000u) ? 0x80000000u : 0xFFFFFFFFu);
        float x = __uint_as_float(u);
        float prob = 1.0f / (1.0f + __expf(-x));
        sm.fckey[p] = ((unsigned long long)__float_as_uint(prob) << 32)
                      | (unsigned int)(~(unsigned int)myidx);
    }
    __syncthreads();
    const int M = min(sm.cnt2, FASTCAP);   // >= KSEL

    // ---- rank by composite key desc == (prob desc, index asc); x4 unrolled ----
    if (tid < M) {
        const unsigned long long mk = sm.fckey[tid];
        int rank = 0;
        const int Mp = (M + 3) & ~3;
        for (int j = 0; j < Mp; j += 4) {
            rank += (sm.fckey[j]     > mk) ? 1 : 0;
            rank += (sm.fckey[j + 1] > mk) ? 1 : 0;
            rank += (sm.fckey[j + 2] > mk) ? 1 : 0;
            rank += (sm.fckey[j + 3] > mk) ? 1 : 0;
        }
        if (rank < TOPK) {
            sm.sval[rank] = __uint_as_float((unsigned int)(mk >> 32));
            sm.sidx[rank] = (int)(~(unsigned int)(mk & 0xFFFFFFFFu));
        }
    }
    __syncthreads();

    const float hh = tsz[2 * b + 0];   // img_h
    const float ww = tsz[2 * b + 1];   // img_w

    // ---- char level: spread scattered ctrl-point gather over 400 threads ----
    if (LEVEL == 2) {
        if (tid < TOPK * 4) {
            const int k = tid >> 2, q = tid & 3;
            const int si = sm.sidx[k];
            float4 v = ((const float4*)(chr_raw + ((size_t)b * NCHR + (size_t)si) * 16))[q];
            v.x *= hh; v.y *= ww; v.z *= hh; v.w *= ww;
            sm.sdat4[k][q] = v;
        }
        __syncthreads();
    }

    // ---- per-detection geometry ----
    if (tid < TOPK) {
        const int k  = tid;
        const int si = sm.sidx[k];
        float x1, y1, x2, y2;
        float4 p;

        if (LEVEL == 1) {
            p = ((const float4*)(blk_raw + ((size_t)b * NBLK + (size_t)(si >> 2)) * 4))[0];
        } else if (LEVEL == 2) {
            p = ((const float4*)(lin_raw + ((size_t)b * NLIN + (size_t)si) * 4))[0];
        }

        if (LEVEL == 2) {
            float ctrl[16];
#pragma unroll
            for (int q = 0; q < 4; ++q) {
                float4 v = sm.sdat4[k][q];
                ctrl[4 * q + 0] = v.x; ctrl[4 * q + 1] = v.y;
                ctrl[4 * q + 2] = v.z; ctrl[4 * q + 3] = v.w;
            }
            float mnx = 1e30f, mny = 1e30f, mxx = -1e30f, mxy = -1e30f;
#pragma unroll
            for (int s = 0; s < 10; ++s) {
                float t  = (float)s * (1.0f / 9.0f);
                float ti = 1.0f - t;
                float b0 = ti * ti * ti;
                float b1 = 3.0f * t * ti * ti;
                float b2 = 3.0f * t * t * ti;
                float b3 = t * t * t;
                float xt = b0 * ctrl[0] + b1 * ctrl[2]  + b2 * ctrl[4]  + b3 * ctrl[6];
                float yt = b0 * ctrl[1] + b1 * ctrl[3]  + b2 * ctrl[5]  + b3 * ctrl[7];
                float xb = b0 * ctrl[8] + b1 * ctrl[10] + b2 * ctrl[12] + b3 * ctrl[14];
                float yb = b0 * ctrl[9] + b1 * ctrl[11] + b2 * ctrl[13] + b3 * ctrl[15];
                mnx = fminf(mnx, fminf(xt, xb));
                mny = fminf(mny, fminf(yt, yb));
                mxx = fmaxf(mxx, fmaxf(xt, xb));
                mxy = fmaxf(mxy, fmaxf(yt, yb));
            }
            x1 = mnx; y1 = mny; x2 = mxx; y2 = mxy;
        } else {
            float4 v = (LEVEL == 0)
                ? ((const float4*)(blk_raw + ((size_t)b * NBLK + (size_t)si) * 4))[0]
                : ((const float4*)(lin_raw + ((size_t)b * NLIN + (size_t)si) * 4))[0];
            x1 = (v.x - 0.5f * v.z) * ww;
            y1 = (v.y - 0.5f * v.w) * hh;
            x2 = (v.x + 0.5f * v.z) * ww;
            y2 = (v.y + 0.5f * v.w) * hh;
            if (LEVEL == 0) {
                x1 = fminf(fmaxf(x1, 0.0f), ww);
                y1 = fminf(fmaxf(y1, 0.0f), hh);
                x2 = fminf(fmaxf(x2, 0.0f), ww);
                y2 = fminf(fmaxf(y2, 0.0f), hh);
            }
            float4 d; d.x = x1; d.y = y1; d.z = x2; d.w = y2;
            sm.sdat4[k][0] = d;
        }

        float4 bx; bx.x = x1; bx.y = y1; bx.z = x2; bx.w = y2;
        sm.sbox4[k] = bx;
        sm.sarea[k] = (x2 - x1) * (y2 - y1);

        bool kp   = sm.sval[k] > 0.1f;
        bool anyk = sm.sval[0] > 0.1f;
        if (!anyk) kp = (k == 0);
        sm.skeep[k] = kp ? 1 : 0;

        if (LEVEL > 0) {
            float px1 = (p.x - 0.5f * p.z) * ww;
            float py1 = (p.y - 0.5f * p.w) * hh;
            float px2 = (p.x + 0.5f * p.z) * ww;
            float py2 = (p.y + 0.5f * p.w) * hh;
            float ix1 = fmaxf(x1, px1);
            float iy1 = fmaxf(y1, py1);
            float ix2 = fminf(x2, px2);
            float iy2 = fminf(y2, py2);
            float inter = fmaxf(ix2 - ix1, 0.0f) * fmaxf(iy2 - iy1, 0.0f);
            float carea = (x2 - x1) * (y2 - y1);
            sm.sbelong[k] = inter / (carea + 1e-6f);
        }
    }
    __syncthreads();

    // ---- belong validity + fallback (lines / chars), parallel argmax ----
    if (LEVEL > 0) {
        const bool in = (tid < TOPK) && (sm.skeep[tid] != 0);
        const float bl = in ? sm.sbelong[tid] : 0.0f;
        int any_vk = __syncthreads_count(in && (bl > 0.6f));
        unsigned long long key = in
            ? (((unsigned long long)__float_as_uint(bl) << 32) | (unsigned int)(~(unsigned int)tid))
            : 0ull;
#pragma unroll
        for (int off = 16; off > 0; off >>= 1) {
            unsigned long long o = __shfl_down_sync(0xFFFFFFFFu, key, off);
            key = (o > key) ? o : key;
        }
        if ((tid & 31) == 0) sm.wkeys[tid >> 5] = key;
        __syncthreads();
        if (tid == 0) {
            unsigned long long best = 0ull;
#pragma unroll
            for (int w = 0; w < 16; ++w) best = (sm.wkeys[w] > best) ? sm.wkeys[w] : best;
            sm.argmax_idx = (best == 0ull) ? 0 : (int)(~(unsigned int)(best & 0xFFFFFFFFu));
        }
        __syncthreads();
        if (tid < TOPK) {
            bool valid = sm.sbelong[tid] > 0.6f;
            if (any_vk == 0) valid = (tid == sm.argmax_idx);
            if (!valid) sm.skeep[tid] = 0;
        }
        __syncthreads();
    }

    // ---- keep ballot + compact kept-index list ----
    if (tid < 128) {
        bool kp = (tid < TOPK) && (sm.skeep[tid] != 0);
        unsigned int m = __ballot_sync(0xFFFFFFFFu, kp);
        if ((tid & 31) == 0) sm.keepw[tid >> 5] = m;
    }
    if (tid < TOPK && sm.skeep[tid]) {
        int p = atomicAdd(&sm.kcnt, 1);
        sm.klist[p] = tid;
    }
    __syncthreads();

    // ---- NMS adjacency: only rows for initially-kept boxes ----
    {
        const int warp = tid >> 5, lane = tid & 31;
        const int ntask = sm.kcnt * 4;
        for (int task = warp; task < ntask; task += NT / 32) {
            const int i = sm.klist[task >> 2], w = task & 3;
            unsigned int m = 0u;
            if (i < 32 * (w + 1)) {
                const int j = w * 32 + lane;
                bool pred = false;
                if (j < TOPK && j > i) {
                    float4 bi_ = sm.sbox4[i];
                    float4 bj_ = sm.sbox4[j];
                    float ix1 = fmaxf(bi_.x, bj_.x);
                    float iy1 = fmaxf(bi_.y, bj_.y);
                    float ix2 = fminf(bi_.z, bj_.z);
                    float iy2 = fminf(bi_.w, bj_.w);
                    float inter = fmaxf(ix2 - ix1, 0.0f) * fmaxf(iy2 - iy1, 0.0f);
                    pred = inter > 0.1f * (sm.sarea[i] + sm.sarea[j] - inter);
                }
                m = __ballot_sync(0xFFFFFFFFu, pred);
            }
            if (lane == 0) sm.adj[i][w] = m;
        }
    }
    __syncthreads();

    // ---- suppression scan: ffs-jump over still-kept boxes only ----
    if (tid == 0) {
        unsigned int kk0 = sm.keepw[0], kk1 = sm.keepw[1], kk2 = sm.keepw[2], kk3 = sm.keepw[3];
        const uint4* adj4 = (const uint4*)sm.adj;
#pragma unroll
        for (int w = 0; w < 4; ++w) {
            unsigned int cur = (w == 0) ? kk0 : (w == 1) ? kk1 : (w == 2) ? kk2 : kk3;
            unsigned int m = cur;
            while (m) {
                int bitp = __ffs(m) - 1;
                int i = 32 * w + bitp;
                uint4 a = adj4[i];
                kk0 &= ~a.x; kk1 &= ~a.y; kk2 &= ~a.z; kk3 &= ~a.w;
                cur = (w == 0) ? kk0 : (w == 1) ? kk1 : (w == 2) ? kk2 : kk3;
                m = cur & ((0xFFFFFFFFu << bitp) << 1);
            }
        }
        sm.keepw[0] = kk0; sm.keepw[1] = kk1; sm.keepw[2] = kk2; sm.keepw[3] = kk3;
    }
    __syncthreads();

    // ---- write outputs ----
    constexpr size_t data_off  = (LEVEL == 0) ? 0      : (LEVEL == 1) ? 38400 : 76800;
    constexpr size_t score_off = (LEVEL == 0) ? 25600  : (LEVEL == 1) ? 64000 : 179200;
    constexpr size_t keep_off  = (LEVEL == 0) ? 32000  : (LEVEL == 1) ? 70400 : 185600;
    const float4 z4 = make_float4(0.f, 0.f, 0.f, 0.f);

    if (LEVEL == 2) {
        float4* dp4 = (float4*)(out + data_off + (size_t)b * TOPK * 16);
        if (tid < TOPK * 4) {
            const int k = tid >> 2, q = tid & 3;
            bool kp = (sm.keepw[k >> 5] >> (k & 31)) & 1u;
            dp4[tid] = kp ? sm.sdat4[k][q] : z4;
        }
    } else {
        float4* dp4 = (float4*)(out + data_off + (size_t)b * TOPK * 4);
        if (tid < TOPK) {
            bool kp = (sm.keepw[tid >> 5] >> (tid & 31)) & 1u;
            dp4[tid] = kp ? sm.sdat4[tid][0] : z4;
        }
    }
    if (tid < TOPK) {
        bool kp = (sm.keepw[tid >> 5] >> (tid & 31)) & 1u;
        out[score_off + (size_t)b * TOPK + tid] = kp ? sm.sval[tid] : 0.0f;
        out[keep_off  + (size_t)b * TOPK + tid] = kp ? 1.0f : 0.0f;
    }
}

__global__ void __launch_bounds__(NT)
postprocess_kernel(const float* __restrict__ blk_logit,
                   const float* __restrict__ lin_logit,
                   const float* __restrict__ chr_logit,
                   const float* __restrict__ blk_raw,
                   const float* __restrict__ lin_raw,
                   const float* __restrict__ chr_raw,
                   const float* __restrict__ tsz,
                   float* __restrict__ out)
{
    __shared__ SharedState sm;
    const int bid = blockIdx.x;
    const int tid = threadIdx.x;
    // heavy levels first in linear bid order: [lin 0-63 | chr 64-127 | blk 128-191]
    // -> no SM co-hosts two heavy CTAs (occ=2 pairing is bid s with bid s+148)
    if (bid < 64) {
        const int b = bid;
        pp_body<32, 1>(sm, b, tid, lin_logit + (size_t)b * NLIN,
                       blk_raw, lin_raw, chr_raw, tsz, out);
    } else if (bid < 128) {
        const int b = bid - 64;
        pp_body<32, 2>(sm, b, tid, chr_logit + (size_t)b * NCHR,
                       blk_raw, lin_raw, chr_raw, tsz, out);
    } else {
        const int b = bid - 128;
        pp_body<8, 0>(sm, b, tid, blk_logit + (size_t)b * NBLK,
                      blk_raw, lin_raw, chr_raw, tsz, out);
    }
}

extern "C" void kernel_launch(void* const* d_in, const int* in_sizes, int n_in,
                              void* d_out, int out_size) {
    (void)in_sizes; (void)n_in; (void)out_size;
    postprocess_kernel<<<192, NT>>>(
        (const float*)d_in[0],   // pred_block_logits
        (const float*)d_in[1],   // pred_line_logits
        (const float*)d_in[2],   // pred_char_logits
        (const float*)d_in[3],   // pred_block
        (const float*)d_in[4],   // pred_line
        (const float*)d_in[5],   // pred_char
        (const float*)d_in[6],   // target_sizes
        (float*)d_out);
}

// round 9
// speedup vs baseline: 2.1253x; 1.0194x over previous
#include <cuda_runtime.h>
#include <math.h>

#define B_IMGS   64
#define NBLK     4096
#define NLIN     16384
#define NCHR     16384
#define TOPK     100
#define KSEL     128      // exact top-K superset size by logit
#define MTGT     160      // stop bisection once survivor count <= this
#define NT       512
#define FASTCAP  512

// threshold guesses, float domain (positive => float cmp == key cmp)
#define TH0 1.5f          // N=4096
#define TH1 2.25f         // N=16384
#define GK0 0xBFC00000u   // fkey(1.5)
#define GH0 0xC0800000u   // fkey(4.0)
#define GK1 0xC0100000u   // fkey(2.25)
#define GH1 0xC0980000u   // fkey(4.75)

// Output layout (float32), reference return order (*blk, *lin, *chr):
//  blk_data [64,100,4]  @ 0       blk_scores @ 25600   blk_keep @ 32000
//  lin_data [64,100,4]  @ 38400   lin_scores @ 64000   lin_keep @ 70400
//  chr_data [64,100,16] @ 76800   chr_scores @ 179200  chr_keep @ 185600

struct __align__(16) SharedState {
    unsigned int adj[TOPK][4];
    float4 sdat4[TOPK][4];
    float4 sbox4[TOPK];
    unsigned long long fckey[FASTCAP];
    unsigned long long wkeys[16];
    uint2 scand[FASTCAP];               // (key, idx)
    float sval[TOPK];
    int   sidx[TOPK];
    float sarea[TOPK];
    float sbelong[TOPK];
    int   skeep[TOPK];
    int   klist[TOPK];
    unsigned int keepw[4];
    int totals[32];
    int cnt;
    int cnt2;
    int kcnt;
    int argmax_idx;
};

__device__ __forceinline__ unsigned int fkey(float f) {
    unsigned int u = __float_as_uint(f);
    return u ^ (((unsigned int)((int)u >> 31)) | 0x80000000u);
}

template<int LOC, int LEVEL>
__device__ __forceinline__ void pp_body(
    SharedState& sm, int b, int tid,
    const float* __restrict__ lb,
    const float* __restrict__ blk_raw,
    const float* __restrict__ lin_raw,
    const float* __restrict__ chr_raw,
    const float* __restrict__ tsz,
    float* __restrict__ out)
{
    const int N = LOC * NT;
    constexpr float        TH = (LEVEL == 0) ? TH0 : TH1;
    constexpr unsigned int GK = (LEVEL == 0) ? GK0 : GK1;
    constexpr unsigned int GH = (LEVEL == 0) ? GH0 : GH1;

    sm.fckey[tid] = 0ull;               // zero-pad for unrolled rank loop
    if (tid < 32) sm.totals[tid] = 0;
    if (tid == 0) { sm.cnt = 0; sm.cnt2 = 0; sm.kcnt = 0; sm.argmax_idx = 0; }
    __syncthreads();

    // ---- streaming threshold filter: float compare, fkey only on survivors ----
    {
        const float4* lb4 = (const float4*)lb;
#pragma unroll
        for (int r4 = 0; r4 < LOC / 4; ++r4) {
            float4 v = lb4[tid + r4 * NT];
            const int base = 4 * (tid + r4 * NT);
            if (v.x >= TH) {
                int p = atomicAdd(&sm.cnt, 1);
                if (p < FASTCAP) sm.scand[p] = make_uint2(fkey(v.x), (unsigned int)(base + 0));
            }
            if (v.y >= TH) {
                int p = atomicAdd(&sm.cnt, 1);
                if (p < FASTCAP) sm.scand[p] = make_uint2(fkey(v.y), (unsigned int)(base + 1));
            }
            if (v.z >= TH) {
                int p = atomicAdd(&sm.cnt, 1);
                if (p < FASTCAP) sm.scand[p] = make_uint2(fkey(v.z), (unsigned int)(base + 2));
            }
            if (v.w >= TH) {
                int p = atomicAdd(&sm.cnt, 1);
                if (p < FASTCAP) sm.scand[p] = make_uint2(fkey(v.w), (unsigned int)(base + 3));
            }
        }
    }
    __syncthreads();
    const int cG = sm.cnt;

    unsigned int lo, hi;
    int cg, cnt_cur;
    if (cG >= KSEL && cG <= FASTCAP) {
        cg = cG; lo = GK; hi = GH; cnt_cur = cG;
    } else {
        // ---- cold fallback: exact bitwise search, re-reading from global ----
        __syncthreads();
        if (tid == 0) sm.cnt = 0;
        __syncthreads();
        unsigned int prefix = 0u;
        cnt_cur = N;
        const float4* lb4 = (const float4*)lb;
        for (int bit = 31; bit >= 0; --bit) {
            if (cnt_cur <= FASTCAP) break;
            unsigned int cand = prefix | (1u << bit);
            unsigned int c = 0;
            for (int r4 = 0; r4 < LOC / 4; ++r4) {
                float4 v = lb4[tid + r4 * NT];
                c += (fkey(v.x) >= cand) + (fkey(v.y) >= cand)
                   + (fkey(v.z) >= cand) + (fkey(v.w) >= cand);
            }
            c = __reduce_add_sync(0xFFFFFFFFu, c);
            if ((tid & 31) == 0 && c) atomicAdd(&sm.totals[bit], (int)c);
            __syncthreads();
            int tot = sm.totals[bit];
            if (tot >= KSEL) { prefix = cand; cnt_cur = tot; }
        }
        for (int r4 = 0; r4 < LOC / 4; ++r4) {
            float4 v = lb4[tid + r4 * NT];
            const int base = 4 * (tid + r4 * NT);
            unsigned int kk[4] = { fkey(v.x), fkey(v.y), fkey(v.z), fkey(v.w) };
#pragma unroll
            for (int c = 0; c < 4; ++c) {
                if (kk[c] >= prefix) {
                    int p = atomicAdd(&sm.cnt, 1);
                    if (p < FASTCAP) sm.scand[p] = make_uint2(kk[c], (unsigned int)(base + c));
                }
            }
        }
        __syncthreads();
        cg = min(sm.cnt, FASTCAP);
        lo = prefix; hi = 0xFFFFFFFFu;
    }

    const unsigned int mykey = (tid < cg) ? sm.scand[tid].x : 0u;
    const int myidx = (tid < cg) ? (int)sm.scand[tid].y : 0;

    // ---- value bisection: shrink survivor count toward [KSEL, MTGT] ----
    int cnt_m = cnt_cur;
    for (int it = 0; it < 6 && cnt_m > MTGT; ++it) {
        unsigned int mid = lo + ((hi - lo) >> 1);
        int c = __syncthreads_count((tid < cg) && (mykey >= mid));
        if (c >= KSEL) { lo = mid; cnt_m = c; } else hi = mid;
    }

    // ---- compact final survivors, fast f32 sigmoid, composite key ----
    if (tid < cg && mykey >= lo) {
        int p = atomicAdd(&sm.cnt2, 1);
        unsigned int u = mykey ^ ((mykey & 0x80000000u) ? 0x80000000u : 0xFFFFFFFFu);
        float x = __uint_as_float(u);
        float prob = 1.0f / (1.0f + __expf(-x));
        sm.fckey[p] = ((unsigned long long)__float_as_uint(prob) << 32)
                      | (unsigned int)(~(unsigned int)myidx);
    }
    __syncthreads();
    const int M = min(sm.cnt2, FASTCAP);   // >= KSEL

    // ---- rank by composite key desc == (prob desc, index asc); x4 unrolled ----
    if (tid < M) {
        const unsigned long long mk = sm.fckey[tid];
        int rank = 0;
        const int Mp = (M + 3) & ~3;
        for (int j = 0; j < Mp; j += 4) {
            rank += (sm.fckey[j]     > mk) ? 1 : 0;
            rank += (sm.fckey[j + 1] > mk) ? 1 : 0;
            rank += (sm.fckey[j + 2] > mk) ? 1 : 0;
            rank += (sm.fckey[j + 3] > mk) ? 1 : 0;
        }
        if (rank < TOPK) {
            sm.sval[rank] = __uint_as_float((unsigned int)(mk >> 32));
            sm.sidx[rank] = (int)(~(unsigned int)(mk & 0xFFFFFFFFu));
        }
    }
    __syncthreads();

    const float hh = tsz[2 * b + 0];   // img_h
    const float ww = tsz[2 * b + 1];   // img_w

    // ---- char level: spread scattered ctrl-point gather over 400 threads ----
    if (LEVEL == 2) {
        if (tid < TOPK * 4) {
            const int k = tid >> 2, q = tid & 3;
            const int si = sm.sidx[k];
            float4 v = ((const float4*)(chr_raw + ((size_t)b * NCHR + (size_t)si) * 16))[q];
            v.x *= hh; v.y *= ww; v.z *= hh; v.w *= ww;
            sm.sdat4[k][q] = v;
        }
        __syncthreads();
    }

    // ---- per-detection geometry ----
    if (tid < TOPK) {
        const int k  = tid;
        const int si = sm.sidx[k];
        float x1, y1, x2, y2;
        float4 p;

        if (LEVEL == 1) {
            p = ((const float4*)(blk_raw + ((size_t)b * NBLK + (size_t)(si >> 2)) * 4))[0];
        } else if (LEVEL == 2) {
            p = ((const float4*)(lin_raw + ((size_t)b * NLIN + (size_t)si) * 4))[0];
        }

        if (LEVEL == 2) {
            float ctrl[16];
#pragma unroll
            for (int q = 0; q < 4; ++q) {
                float4 v = sm.sdat4[k][q];
                ctrl[4 * q + 0] = v.x; ctrl[4 * q + 1] = v.y;
                ctrl[4 * q + 2] = v.z; ctrl[4 * q + 3] = v.w;
            }
            float mnx = 1e30f, mny = 1e30f, mxx = -1e30f, mxy = -1e30f;
#pragma unroll
            for (int s = 0; s < 10; ++s) {
                float t  = (float)s * (1.0f / 9.0f);
                float ti = 1.0f - t;
                float b0 = ti * ti * ti;
                float b1 = 3.0f * t * ti * ti;
                float b2 = 3.0f * t * t * ti;
                float b3 = t * t * t;
                float xt = b0 * ctrl[0] + b1 * ctrl[2]  + b2 * ctrl[4]  + b3 * ctrl[6];
                float yt = b0 * ctrl[1] + b1 * ctrl[3]  + b2 * ctrl[5]  + b3 * ctrl[7];
                float xb = b0 * ctrl[8] + b1 * ctrl[10] + b2 * ctrl[12] + b3 * ctrl[14];
                float yb = b0 * ctrl[9] + b1 * ctrl[11] + b2 * ctrl[13] + b3 * ctrl[15];
                mnx = fminf(mnx, fminf(xt, xb));
                mny = fminf(mny, fminf(yt, yb));
                mxx = fmaxf(mxx, fmaxf(xt, xb));
                mxy = fmaxf(mxy, fmaxf(yt, yb));
            }
            x1 = mnx; y1 = mny; x2 = mxx; y2 = mxy;
        } else {
            float4 v = (LEVEL == 0)
                ? ((const float4*)(blk_raw + ((size_t)b * NBLK + (size_t)si) * 4))[0]
                : ((const float4*)(lin_raw + ((size_t)b * NLIN + (size_t)si) * 4))[0];
            x1 = (v.x - 0.5f * v.z) * ww;
            y1 = (v.y - 0.5f * v.w) * hh;
            x2 = (v.x + 0.5f * v.z) * ww;
            y2 = (v.y + 0.5f * v.w) * hh;
            if (LEVEL == 0) {
                x1 = fminf(fmaxf(x1, 0.0f), ww);
                y1 = fminf(fmaxf(y1, 0.0f), hh);
                x2 = fminf(fmaxf(x2, 0.0f), ww);
                y2 = fminf(fmaxf(y2, 0.0f), hh);
            }
            float4 d; d.x = x1; d.y = y1; d.z = x2; d.w = y2;
            sm.sdat4[k][0] = d;
        }

        float4 bx; bx.x = x1; bx.y = y1; bx.z = x2; bx.w = y2;
        sm.sbox4[k] = bx;
        sm.sarea[k] = (x2 - x1) * (y2 - y1);

        bool kp   = sm.sval[k] > 0.1f;
        bool anyk = sm.sval[0] > 0.1f;
        if (!anyk) kp = (k == 0);
        sm.skeep[k] = kp ? 1 : 0;

        if (LEVEL > 0) {
            float px1 = (p.x - 0.5f * p.z) * ww;
            float py1 = (p.y - 0.5f * p.w) * hh;
            float px2 = (p.x + 0.5f * p.z) * ww;
            float py2 = (p.y + 0.5f * p.w) * hh;
            float ix1 = fmaxf(x1, px1);
            float iy1 = fmaxf(y1, py1);
            float ix2 = fminf(x2, px2);
            float iy2 = fminf(y2, py2);
            float inter = fmaxf(ix2 - ix1, 0.0f) * fmaxf(iy2 - iy1, 0.0f);
            float carea = (x2 - x1) * (y2 - y1);
            sm.sbelong[k] = inter / (carea + 1e-6f);
        }
    }
    __syncthreads();

    // ---- belong validity + fallback (lines / chars), parallel argmax ----
    if (LEVEL > 0) {
        const bool in = (tid < TOPK) && (sm.skeep[tid] != 0);
        const float bl = in ? sm.sbelong[tid] : 0.0f;
        int any_vk = __syncthreads_count(in && (bl > 0.6f));
        unsigned long long key = in
            ? (((unsigned long long)__float_as_uint(bl) << 32) | (unsigned int)(~(unsigned int)tid))
            : 0ull;
#pragma unroll
        for (int off = 16; off > 0; off >>= 1) {
            unsigned long long o = __shfl_down_sync(0xFFFFFFFFu, key, off);
            key = (o > key) ? o : key;
        }
        if ((tid & 31) == 0) sm.wkeys[tid >> 5] = key;
        __syncthreads();
        if (tid == 0) {
            unsigned long long best = 0ull;
#pragma unroll
            for (int w = 0; w < 16; ++w) best = (sm.wkeys[w] > best) ? sm.wkeys[w] : best;
            sm.argmax_idx = (best == 0ull) ? 0 : (int)(~(unsigned int)(best & 0xFFFFFFFFu));
        }
        __syncthreads();
        if (tid < TOPK) {
            bool valid = sm.sbelong[tid] > 0.6f;
            if (any_vk == 0) valid = (tid == sm.argmax_idx);
            if (!valid) sm.skeep[tid] = 0;
        }
        __syncthreads();
    }

    // ---- keep ballot + compact kept-index list ----
    if (tid < 128) {
        bool kp = (tid < TOPK) && (sm.skeep[tid] != 0);
        unsigned int m = __ballot_sync(0xFFFFFFFFu, kp);
        if ((tid & 31) == 0) sm.keepw[tid >> 5] = m;
    }
    if (tid < TOPK && sm.skeep[tid]) {
        int p = atomicAdd(&sm.kcnt, 1);
        sm.klist[p] = tid;
    }
    __syncthreads();

    // ---- NMS adjacency: only rows for initially-kept boxes ----
    {
        const int warp = tid >> 5, lane = tid & 31;
        const int ntask = sm.kcnt * 4;
        for (int task = warp; task < ntask; task += NT / 32) {
            const int i = sm.klist[task >> 2], w = task & 3;
            unsigned int m = 0u;
            if (i < 32 * (w + 1)) {
                const int j = w * 32 + lane;
                bool pred = false;
                if (j < TOPK && j > i) {
                    float4 bi_ = sm.sbox4[i];
                    float4 bj_ = sm.sbox4[j];
                    float ix1 = fmaxf(bi_.x, bj_.x);
                    float iy1 = fmaxf(bi_.y, bj_.y);
                    float ix2 = fminf(bi_.z, bj_.z);
                    float iy2 = fminf(bi_.w, bj_.w);
                    float inter = fmaxf(ix2 - ix1, 0.0f) * fmaxf(iy2 - iy1, 0.0f);
                    pred = inter > 0.1f * (sm.sarea[i] + sm.sarea[j] - inter);
                }
                m = __ballot_sync(0xFFFFFFFFu, pred);
            }
            if (lane == 0) sm.adj[i][w] = m;
        }
    }
    __syncthreads();

    // ---- suppression scan: ffs-jump over still-kept boxes only ----
    if (tid == 0) {
        unsigned int kk0 = sm.keepw[0], kk1 = sm.keepw[1], kk2 = sm.keepw[2], kk3 = sm.keepw[3];
        const uint4* adj4 = (const uint4*)sm.adj;
#pragma unroll
        for (int w = 0; w < 4; ++w) {
            unsigned int cur = (w == 0) ? kk0 : (w == 1) ? kk1 : (w == 2) ? kk2 : kk3;
            unsigned int m = cur;
            while (m) {
                int bitp = __ffs(m) - 1;
                int i = 32 * w + bitp;
                uint4 a = adj4[i];
                kk0 &= ~a.x; kk1 &= ~a.y; kk2 &= ~a.z; kk3 &= ~a.w;
                cur = (w == 0) ? kk0 : (w == 1) ? kk1 : (w == 2) ? kk2 : kk3;
                m = cur & ((0xFFFFFFFFu << bitp) << 1);
            }
        }
        sm.keepw[0] = kk0; sm.keepw[1] = kk1; sm.keepw[2] = kk2; sm.keepw[3] = kk3;
    }
    __syncthreads();

    // ---- write outputs ----
    constexpr size_t data_off  = (LEVEL == 0) ? 0      : (LEVEL == 1) ? 38400 : 76800;
    constexpr size_t score_off = (LEVEL == 0) ? 25600  : (LEVEL == 1) ? 64000 : 179200;
    constexpr size_t keep_off  = (LEVEL == 0) ? 32000  : (LEVEL == 1) ? 70400 : 185600;
    const float4 z4 = make_float4(0.f, 0.f, 0.f, 0.f);

    if (LEVEL == 2) {
        float4* dp4 = (float4*)(out + data_off + (size_t)b * TOPK * 16);
        if (tid < TOPK * 4) {
            const int k = tid >> 2, q = tid & 3;
            bool kp = (sm.keepw[k >> 5] >> (k & 31)) & 1u;
            dp4[tid] = kp ? sm.sdat4[k][q] : z4;
        }
    } else {
        float4* dp4 = (float4*)(out + data_off + (size_t)b * TOPK * 4);
        if (tid < TOPK) {
            bool kp = (sm.keepw[tid >> 5] >> (tid & 31)) & 1u;
            dp4[tid] = kp ? sm.sdat4[tid][0] : z4;
        }
    }
    if (tid < TOPK) {
        bool kp = (sm.keepw[tid >> 5] >> (tid & 31)) & 1u;
        out[score_off + (size_t)b * TOPK + tid] = kp ? sm.sval[tid] : 0.0f;
        out[keep_off  + (size_t)b * TOPK + tid] = kp ? 1.0f : 0.0f;
    }
}

__global__ void __launch_bounds__(NT, 3)
postprocess_kernel(const float* __restrict__ blk_logit,
                   const float* __restrict__ lin_logit,
                   const float* __restrict__ chr_logit,
                   const float* __restrict__ blk_raw,
                   const float* __restrict__ lin_raw,
                   const float* __restrict__ chr_raw,
                   const float* __restrict__ tsz,
                   float* __restrict__ out)
{
    __shared__ SharedState sm;
    const int b     = blockIdx.x;
    const int level = blockIdx.y;
    const int tid   = threadIdx.x;

    if (level == 0) {
        pp_body<8, 0>(sm, b, tid, blk_logit + (size_t)b * NBLK,
                      blk_raw, lin_raw, chr_raw, tsz, out);
    } else if (level == 1) {
        pp_body<32, 1>(sm, b, tid, lin_logit + (size_t)b * NLIN,
                       blk_raw, lin_raw, chr_raw, tsz, out);
    } else {
        pp_body<32, 2>(sm, b, tid, chr_logit + (size_t)b * NCHR,
                       blk_raw, lin_raw, chr_raw, tsz, out);
    }
}

extern "C" void kernel_launch(void* const* d_in, const int* in_sizes, int n_in,
                              void* d_out, int out_size) {
    (void)in_sizes; (void)n_in; (void)out_size;
    postprocess_kernel<<<dim3(B_IMGS, 3), NT>>>(
        (const float*)d_in[0],   // pred_block_logits
        (const float*)d_in[1],   // pred_line_logits
        (const float*)d_in[2],   // pred_char_logits
        (const float*)d_in[3],   // pred_block
        (const float*)d_in[4],   // pred_line
        (const float*)d_in[5],   // pred_char
        (const float*)d_in[6],   // target_sizes
        (float*)d_out);
}